// round 1
// baseline (speedup 1.0000x reference)
#include <cuda_runtime.h>
#include <math.h>

#define NN 768
#define C1 64
#define C2 128

// ---------------- scratch (device globals; no allocation allowed) ----------------
__device__ float g_q[C1*NN], g_k[C1*NN], g_v[C1*NN], g_vT[NN*C1];
__device__ float g_Qp[C1*NN], g_Kp[C1*NN];
__device__ float g_A[C2*NN], g_Bm[C2*NN];
__device__ float g_scl1[C2], g_bias1[C2];
__device__ float g_Sq[NN], g_Sk[NN];
__device__ float g_av[C1*NN];
__device__ float g_avp[4*C1*NN];
__device__ float g_av2[C1*NN];
__device__ float g_g1[C2*NN];

// ---------------- helpers ----------------
__device__ __forceinline__ float bsum_buf(float v, volatile float* sb) {
    #pragma unroll
    for (int o = 16; o; o >>= 1) v += __shfl_xor_sync(0xffffffffu, v, o);
    if ((threadIdx.x & 31) == 0) sb[threadIdx.x >> 5] = v;
    __syncthreads();
    if (threadIdx.x == 0) {
        float s = sb[0];
        #pragma unroll
        for (int i = 1; i < 8; i++) s += sb[i];
        sb[0] = s;
    }
    __syncthreads();
    return sb[0];
}

// Generic small GEMM body: 4 output rows per block, 256 threads, N=768 columns.
// Y[r,n] = sum_i W[r*ldw+i] * X[i*768+n] + bias[r] (+ addsrc[r,n])
__device__ __forceinline__ void gemm_rows4(
    const float* __restrict__ W, int ldw, int K,
    const float* __restrict__ X,
    const float* __restrict__ bias,
    const float* __restrict__ addsrc,
    float* __restrict__ Y)
{
    __shared__ float ws[4 * 128];
    int tid = threadIdx.x;
    for (int idx = tid; idx < 4 * K; idx += 256)
        ws[idx] = W[(idx / K) * ldw + (idx % K)];
    __syncthreads();

    float acc[4][3] = {};
    for (int i = 0; i < K; i++) {
        float x0 = X[i * NN + tid];
        float x1 = X[i * NN + tid + 256];
        float x2 = X[i * NN + tid + 512];
        #pragma unroll
        for (int r = 0; r < 4; r++) {
            float w = ws[r * K + i];
            acc[r][0] = fmaf(w, x0, acc[r][0]);
            acc[r][1] = fmaf(w, x1, acc[r][1]);
            acc[r][2] = fmaf(w, x2, acc[r][2]);
        }
    }
    #pragma unroll
    for (int r = 0; r < 4; r++) {
        float bb = bias ? bias[r] : 0.f;
        #pragma unroll
        for (int j = 0; j < 3; j++) {
            int n = tid + j * 256;
            float val = acc[r][j] + bb;
            if (addsrc) val += addsrc[r * NN + n];
            Y[r * NN + n] = val;
        }
    }
}

// ---------------- stage kernels ----------------

// q,k,v 1x1 convs. 48 blocks (rows 0..191 in groups of 64).
__global__ void k_qkv(const float* __restrict__ desc1, const float* __restrict__ desc2,
                      const float* __restrict__ qw, const float* __restrict__ qb,
                      const float* __restrict__ kw, const float* __restrict__ kb,
                      const float* __restrict__ vw, const float* __restrict__ vb)
{
    int ro = blockIdx.x * 4;
    int grp = ro >> 6;
    int lr = ro & 63;
    const float *W, *X, *B; float* Y;
    if (grp == 0)      { W = qw; X = desc1; B = qb; Y = g_q; }
    else if (grp == 1) { W = kw; X = desc2; B = kb; Y = g_k; }
    else               { W = vw; X = desc2; B = vb; Y = g_v; }
    gemm_rows4(W + lr * 64, 64, 64, X, B + lr, nullptr, Y + lr * NN);
}

// per-channel 1-D stats of q (c<64) / k (c>=64) -> composite inorm+bnorm scale/bias. 128 blocks.
__global__ void k_stats1(const float* __restrict__ bn1g, const float* __restrict__ bn1b)
{
    int c = blockIdx.x;
    const float* src = (c < 64) ? (g_q + c * NN) : (g_k + (c - 64) * NN);
    float s = 0.f, s2 = 0.f;
    #pragma unroll
    for (int j = 0; j < 3; j++) {
        float x = src[threadIdx.x + j * 256];
        s += x; s2 += x * x;
    }
    __shared__ float r1[8], r2[8];
    s  = bsum_buf(s,  r1);
    s2 = bsum_buf(s2, r2);
    if (threadIdx.x == 0) {
        float m = s * (1.f / NN);
        float v = s2 * (1.f / NN) - m * m;
        float si = rsqrtf(v + 1e-3f);
        float vb = v * si * si;
        float sb = rsqrtf(vb + 1e-5f);
        float scale = si * sb * bn1g[c];
        g_scl1[c] = scale;
        g_bias1[c] = -m * scale + bn1b[c];
    }
}

// per-n: Q'/K' = relu(norm), v transpose, shot sums Sq/Sk. 768 blocks x 128 threads.
__global__ void k_prep(const float* __restrict__ shw)
{
    int n = blockIdx.x;
    int tid = threadIdx.x;
    __shared__ float red[128];
    float term;
    if (tid < 64) {
        float qv = g_q[tid * NN + n];
        g_Qp[tid * NN + n] = fmaxf(fmaf(g_scl1[tid], qv, g_bias1[tid]), 0.f);
        g_vT[n * 64 + tid] = g_v[tid * NN + n];
        term = shw[tid] * qv;
    } else {
        int c = tid - 64;
        float kv = g_k[c * NN + n];
        g_Kp[c * NN + n] = fmaxf(fmaf(g_scl1[tid], kv, g_bias1[tid]), 0.f);
        term = shw[tid] * kv;
    }
    red[tid] = term;
    __syncthreads();
    if (tid == 0) {
        float s = 0.f;
        #pragma unroll
        for (int i = 0; i < 64; i++) s += red[i];
        g_Sq[n] = s;
    }
    if (tid == 64) {
        float s = 0.f;
        #pragma unroll
        for (int i = 64; i < 128; i++) s += red[i];
        g_Sk[n] = s;
    }
}

// A = w1[:, :64] @ Q'  ;  B = w1[:, 64:] @ K' + b1.  64 blocks (256 virtual rows).
__global__ void k_AB(const float* __restrict__ w1, const float* __restrict__ b1)
{
    int vr = blockIdx.x * 4;
    if (vr < 128)
        gemm_rows4(w1 + vr * 128, 128, 64, g_Qp, nullptr, nullptr, g_A + vr * NN);
    else {
        int o = vr - 128;
        gemm_rows4(w1 + o * 128 + 64, 128, 64, g_Kp, b1 + o, nullptr, g_Bm + o * NN);
    }
}

// Stage-2 composite norm from separable stats; rewrite A,B in place as tilde forms. 128 blocks.
__global__ void k_stats2(const float* __restrict__ bn2g, const float* __restrict__ bn2b)
{
    int o = blockIdx.x;
    int tid = threadIdx.x;
    float sA = 0.f, qA = 0.f, sB = 0.f, qB = 0.f;
    #pragma unroll
    for (int j = 0; j < 3; j++) {
        float a = g_A[o * NN + tid + j * 256];
        float b = g_Bm[o * NN + tid + j * 256];
        sA += a; qA += a * a; sB += b; qB += b * b;
    }
    __shared__ float r1[8], r2[8], r3[8], r4[8];
    sA = bsum_buf(sA, r1); qA = bsum_buf(qA, r2);
    sB = bsum_buf(sB, r3); qB = bsum_buf(qB, r4);
    __shared__ float sc_b[2];
    if (tid == 0) {
        float mA = sA * (1.f / NN), mB = sB * (1.f / NN);
        float vA = qA * (1.f / NN) - mA * mA;
        float vB = qB * (1.f / NN) - mB * mB;
        float m2 = mA + mB, v2 = vA + vB;   // stats of A[n]+B[m] over the product grid
        float si = rsqrtf(v2 + 1e-3f);
        float vb = v2 * si * si;
        float sb = rsqrtf(vb + 1e-5f);
        float scale = si * sb * bn2g[o];
        sc_b[0] = scale;
        sc_b[1] = -m2 * scale + bn2b[o];
    }
    __syncthreads();
    float scale = sc_b[0], bias = sc_b[1];
    #pragma unroll
    for (int j = 0; j < 3; j++) {
        int idx = o * NN + tid + j * 256;
        g_A[idx]  = fmaf(scale, g_A[idx], bias);  // Ã carries the full bias
        g_Bm[idx] = scale * g_Bm[idx];            // B̃
    }
}

// score_pre[n,m] = sum_o w2[o]*relu(Ã[o,n]+B̃[o,m]) + b2 + bs + Sq[n] + Sk[m]
// 32x32 tiles, 2x2 register tiles, grid (24,24).
__global__ void k_score(const float* __restrict__ w2, const float* __restrict__ b2p,
                        const float* __restrict__ bsp, float* __restrict__ out_score)
{
    __shared__ float As[128][32];
    __shared__ float Bs[128][32];
    __shared__ float w2s[128];
    __shared__ float Sqs[32], Sks[32];
    int tid = threadIdx.x;
    int n0 = blockIdx.y * 32, m0 = blockIdx.x * 32;

    for (int idx = tid; idx < 128 * 32; idx += 256) {
        int o = idx >> 5, t = idx & 31;
        As[o][t] = g_A[o * NN + n0 + t];
        Bs[o][t] = g_Bm[o * NN + m0 + t];
    }
    if (tid < 128) w2s[tid] = w2[tid];
    if (tid < 32) { Sqs[tid] = g_Sq[n0 + tid]; Sks[tid] = g_Sk[m0 + tid]; }
    __syncthreads();

    int tx = tid & 15;   // m
    int ty = tid >> 4;   // n
    float acc00 = 0.f, acc01 = 0.f, acc10 = 0.f, acc11 = 0.f;
    #pragma unroll 4
    for (int o = 0; o < 128; o++) {
        float2 a = *(const float2*)&As[o][ty * 2];
        float2 b = *(const float2*)&Bs[o][tx * 2];
        float w = w2s[o];
        acc00 = fmaf(w, fmaxf(a.x + b.x, 0.f), acc00);
        acc01 = fmaf(w, fmaxf(a.x + b.y, 0.f), acc01);
        acc10 = fmaf(w, fmaxf(a.y + b.x, 0.f), acc10);
        acc11 = fmaf(w, fmaxf(a.y + b.y, 0.f), acc11);
    }
    float cc = b2p[0] + bsp[0];
    float bq0 = Sqs[ty * 2] + cc, bq1 = Sqs[ty * 2 + 1] + cc;
    float bk0 = Sks[tx * 2],      bk1 = Sks[tx * 2 + 1];
    int n = n0 + ty * 2, m = m0 + tx * 2;
    float2 v0 = make_float2(acc00 + bq0 + bk0, acc01 + bq0 + bk1);
    float2 v1 = make_float2(acc10 + bq1 + bk0, acc11 + bq1 + bk1);
    *(float2*)&out_score[n * NN + m]       = v0;
    *(float2*)&out_score[(n + 1) * NN + m] = v1;
}

// warp-per-row softmax, in place. 96 blocks x 256.
__global__ void k_softmax(float* __restrict__ score)
{
    int row = blockIdx.x * 8 + (threadIdx.x >> 5);
    int lane = threadIdx.x & 31;
    float* p = score + row * NN;
    float v[24];
    float mx = -1e30f;
    #pragma unroll
    for (int i = 0; i < 24; i++) { v[i] = p[lane + i * 32]; mx = fmaxf(mx, v[i]); }
    #pragma unroll
    for (int o = 16; o; o >>= 1) mx = fmaxf(mx, __shfl_xor_sync(0xffffffffu, mx, o));
    float s = 0.f;
    #pragma unroll
    for (int i = 0; i < 24; i++) { v[i] = __expf(v[i] - mx); s += v[i]; }
    #pragma unroll
    for (int o = 16; o; o >>= 1) s += __shfl_xor_sync(0xffffffffu, s, o);
    float inv = 1.f / s;
    #pragma unroll
    for (int i = 0; i < 24; i++) p[lane + i * 32] = v[i] * inv;
}

// av[d,n] = sum_m P[n,m] * vT[m,d].  split-k: 48 n-tiles x 4 k-splits = 192 blocks.
__global__ void k_av(const float* __restrict__ score)
{
    int bx = blockIdx.x;
    int nt = bx % 48, ks = bx / 48;
    int n0 = nt * 16;
    int tid = threadIdx.x;
    __shared__ float Vs[64][64];
    __shared__ float Ps[16][64];
    int d0  = (tid & 31) * 2;        // lane -> d pair (coalesced/conflict-free)
    int nl0 = (tid >> 5) * 2;        // warp -> n pair (broadcast)
    float a00 = 0.f, a01 = 0.f, a10 = 0.f, a11 = 0.f;
    for (int c = 0; c < 3; c++) {
        int mb = ks * 192 + c * 64;
        for (int idx = tid; idx < 64 * 64; idx += 256)
            Vs[idx >> 6][idx & 63] = g_vT[(mb + (idx >> 6)) * 64 + (idx & 63)];
        for (int idx = tid; idx < 16 * 64; idx += 256)
            Ps[idx >> 6][idx & 63] = score[(n0 + (idx >> 6)) * NN + mb + (idx & 63)];
        __syncthreads();
        #pragma unroll 4
        for (int m = 0; m < 64; m++) {
            float2 vv = *(const float2*)&Vs[m][d0];
            float p0 = Ps[nl0][m], p1 = Ps[nl0 + 1][m];
            a00 = fmaf(p0, vv.x, a00); a01 = fmaf(p0, vv.y, a01);
            a10 = fmaf(p1, vv.x, a10); a11 = fmaf(p1, vv.y, a11);
        }
        __syncthreads();
    }
    float* dst = g_avp + ks * (C1 * NN);
    dst[d0 * NN + n0 + nl0]           = a00;
    dst[(d0 + 1) * NN + n0 + nl0]     = a01;
    dst[d0 * NN + n0 + nl0 + 1]       = a10;
    dst[(d0 + 1) * NN + n0 + nl0 + 1] = a11;
}

__global__ void k_avred()
{
    int i = blockIdx.x * 256 + threadIdx.x;
    g_av[i] = g_avp[i] + g_avp[C1 * NN + i] + g_avp[2 * C1 * NN + i] + g_avp[3 * C1 * NN + i];
}

// mh conv: av2 = mh_w @ av + mh_b. 16 blocks.
__global__ void k_mh(const float* __restrict__ mhw, const float* __restrict__ mhb)
{
    int row0 = blockIdx.x * 4;
    gemm_rows4(mhw + row0 * 64, 64, 64, g_av, mhb + row0, nullptr, g_av2 + row0 * NN);
}

// g1 = cat_w1 @ [desc1; av2] + cat_b1. 32 blocks, K=128 stitched.
__global__ void k_cat1(const float* __restrict__ w1, const float* __restrict__ desc1,
                       const float* __restrict__ b1)
{
    int row0 = blockIdx.x * 4;
    int tid = threadIdx.x;
    __shared__ float ws[512];
    for (int idx = tid; idx < 512; idx += 256)
        ws[idx] = w1[(row0 + (idx >> 7)) * 128 + (idx & 127)];
    __syncthreads();
    float acc[4][3] = {};
    for (int i = 0; i < 64; i++) {
        float x0 = desc1[i * NN + tid];
        float x1 = desc1[i * NN + tid + 256];
        float x2 = desc1[i * NN + tid + 512];
        #pragma unroll
        for (int r = 0; r < 4; r++) {
            float w = ws[r * 128 + i];
            acc[r][0] = fmaf(w, x0, acc[r][0]);
            acc[r][1] = fmaf(w, x1, acc[r][1]);
            acc[r][2] = fmaf(w, x2, acc[r][2]);
        }
    }
    for (int i = 0; i < 64; i++) {
        float x0 = g_av2[i * NN + tid];
        float x1 = g_av2[i * NN + tid + 256];
        float x2 = g_av2[i * NN + tid + 512];
        #pragma unroll
        for (int r = 0; r < 4; r++) {
            float w = ws[r * 128 + 64 + i];
            acc[r][0] = fmaf(w, x0, acc[r][0]);
            acc[r][1] = fmaf(w, x1, acc[r][1]);
            acc[r][2] = fmaf(w, x2, acc[r][2]);
        }
    }
    #pragma unroll
    for (int r = 0; r < 4; r++) {
        float bb = b1[row0 + r];
        #pragma unroll
        for (int j = 0; j < 3; j++)
            g_g1[(row0 + r) * NN + tid + j * 256] = acc[r][j] + bb;
    }
}

// bnorm1d stats + relu in place on g1. 128 blocks.
__global__ void k_bn1d(const float* __restrict__ cbg, const float* __restrict__ cbb)
{
    int o = blockIdx.x;
    int tid = threadIdx.x;
    float s = 0.f, s2 = 0.f;
    #pragma unroll
    for (int j = 0; j < 3; j++) {
        float x = g_g1[o * NN + tid + j * 256];
        s += x; s2 += x * x;
    }
    __shared__ float r1[8], r2[8];
    s = bsum_buf(s, r1); s2 = bsum_buf(s2, r2);
    __shared__ float sc_b[2];
    if (tid == 0) {
        float m = s * (1.f / NN);
        float v = s2 * (1.f / NN) - m * m;
        float scale = rsqrtf(v + 1e-5f) * cbg[o];
        sc_b[0] = scale;
        sc_b[1] = -m * scale + cbb[o];
    }
    __syncthreads();
    float scale = sc_b[0], bias = sc_b[1];
    #pragma unroll
    for (int j = 0; j < 3; j++) {
        int idx = o * NN + tid + j * 256;
        g_g1[idx] = fmaxf(fmaf(scale, g_g1[idx], bias), 0.f);
    }
}

// out_desc = desc1 + cat_w2 @ relu_g1 + cat_b2. 16 blocks.
__global__ void k_final(const float* __restrict__ cw2, const float* __restrict__ cb2,
                        const float* __restrict__ desc1, float* __restrict__ out)
{
    int row0 = blockIdx.x * 4;
    gemm_rows4(cw2 + row0 * 128, 128, 128, g_g1, cb2 + row0, desc1 + row0 * NN, out + row0 * NN);
}

// ---------------- launch ----------------
extern "C" void kernel_launch(void* const* d_in, const int* in_sizes, int n_in,
                              void* d_out, int out_size)
{
    const float* desc1 = (const float*)d_in[0];
    const float* desc2 = (const float*)d_in[1];
    const float* qw  = (const float*)d_in[2];  const float* qb  = (const float*)d_in[3];
    const float* kw  = (const float*)d_in[4];  const float* kb  = (const float*)d_in[5];
    const float* vw  = (const float*)d_in[6];  const float* vb  = (const float*)d_in[7];
    const float* mhw = (const float*)d_in[8];  const float* mhb = (const float*)d_in[9];
    const float* cw1 = (const float*)d_in[10]; const float* cb1 = (const float*)d_in[11];
    const float* cbg = (const float*)d_in[12]; const float* cbb = (const float*)d_in[13];
    const float* cw2 = (const float*)d_in[14]; const float* cb2 = (const float*)d_in[15];
    const float* shw = (const float*)d_in[16]; const float* shb = (const float*)d_in[17];
    const float* bn1g = (const float*)d_in[18]; const float* bn1b = (const float*)d_in[19];
    const float* sw1 = (const float*)d_in[20]; const float* sb1 = (const float*)d_in[21];
    const float* bn2g = (const float*)d_in[22]; const float* bn2b = (const float*)d_in[23];
    const float* sw2 = (const float*)d_in[24]; const float* sb2 = (const float*)d_in[25];

    float* out = (float*)d_out;
    float* out_desc  = out;               // [64, 768] -> desc1_new
    float* out_score = out + C1 * NN;     // [768, 768] -> softmax scores

    k_qkv<<<48, 256>>>(desc1, desc2, qw, qb, kw, kb, vw, vb);
    k_stats1<<<128, 256>>>(bn1g, bn1b);
    k_prep<<<NN, 128>>>(shw);
    k_AB<<<64, 256>>>(sw1, sb1);
    k_stats2<<<128, 256>>>(bn2g, bn2b);
    k_score<<<dim3(24, 24), 256>>>(sw2, sb2, shb, out_score);
    k_softmax<<<96, 256>>>(out_score);
    k_av<<<192, 256>>>(out_score);
    k_avred<<<192, 256>>>();
    k_mh<<<16, 256>>>(mhw, mhb);
    k_cat1<<<32, 256>>>(cw1, desc1, cb1);
    k_bn1d<<<128, 256>>>(cbg, cbb);
    k_final<<<16, 256>>>(cw2, cb2, desc1, out_desc);
}

// round 2
// speedup vs baseline: 1.4150x; 1.4150x over previous
#include <cuda_runtime.h>
#include <math.h>

#define NN 768

// ---------------- scratch ----------------
__device__ float g_q[64*NN], g_k[64*NN], g_vT[NN*64];
__device__ float g_A[128*NN], g_B[128*NN];
__device__ float g_scl1[128], g_bias1[128];
__device__ float g_scl2[128], g_bias2[128];
__device__ float g_Sq[NN], g_Sk[NN];
__device__ float g_fq[64], g_fk[64], g_fc[2];
__device__ float g_av[64*NN], g_avp[4*64*NN], g_av2[64*NN], g_g1[128*NN];

// ---------------- helpers ----------------
__device__ __forceinline__ float bsum_buf(float v, volatile float* sb) {
    #pragma unroll
    for (int o = 16; o; o >>= 1) v += __shfl_xor_sync(0xffffffffu, v, o);
    if ((threadIdx.x & 31) == 0) sb[threadIdx.x >> 5] = v;
    __syncthreads();
    if (threadIdx.x == 0) {
        float s = sb[0];
        #pragma unroll
        for (int i = 1; i < 8; i++) s += sb[i];
        sb[0] = s;
    }
    __syncthreads();
    return sb[0];
}

// Stage X[64][128] tile (cols c0..c0+127) from row-major [*,768] source.
__device__ __forceinline__ void fill_X(float* Xs, const float* __restrict__ X, int c0) {
    #pragma unroll
    for (int v = threadIdx.x; v < 2048; v += 256) {
        int i = v >> 5, c4 = (v & 31) << 2;
        *(float4*)&Xs[i*128 + c4] = *(const float4*)&X[i*NN + c0 + c4];
    }
}

// Same, applying relu(s1[i]*x + b1[i]) per row i (s1/b1 in smem).
__device__ __forceinline__ void fill_Xnorm(float* Xs, const float* __restrict__ X, int c0,
                                           const float* s1, const float* b1) {
    #pragma unroll
    for (int v = threadIdx.x; v < 2048; v += 256) {
        int i = v >> 5, c4 = (v & 31) << 2;
        float s = s1[i], b = b1[i];
        float4 x = *(const float4*)&X[i*NN + c0 + c4];
        x.x = fmaxf(fmaf(s, x.x, b), 0.f);
        x.y = fmaxf(fmaf(s, x.y, b), 0.f);
        x.z = fmaxf(fmaf(s, x.z, b), 0.f);
        x.w = fmaxf(fmaf(s, x.w, b), 0.f);
        *(float4*)&Xs[i*128 + c4] = x;
    }
}

// Stage transposed weight tile wT[64][16]: wT[i*16+r] = W[(o0+r)*ldw + koff + i]
__device__ __forceinline__ void fill_W(float* wT, const float* __restrict__ W,
                                       int ldw, int o0, int koff) {
    #pragma unroll
    for (int v = threadIdx.x; v < 1024; v += 256) {
        int i = v >> 4, r = v & 15;
        wT[v] = W[(o0 + r) * ldw + koff + i];
    }
}

// 16 rows x 128 cols tile, K=64, 8 accs/thread.
__device__ __forceinline__ void gemm16_acc(const float* Xs, const float* wT, float acc[8]) {
    int c = threadIdx.x & 127, rg = threadIdx.x >> 7;
    const float* wp = wT + rg * 8;
    #pragma unroll 16
    for (int i = 0; i < 64; i++) {
        float x = Xs[i*128 + c];
        float4 w0 = *(const float4*)(wp + i*16);
        float4 w1 = *(const float4*)(wp + i*16 + 4);
        acc[0] = fmaf(w0.x, x, acc[0]);
        acc[1] = fmaf(w0.y, x, acc[1]);
        acc[2] = fmaf(w0.z, x, acc[2]);
        acc[3] = fmaf(w0.w, x, acc[3]);
        acc[4] = fmaf(w1.x, x, acc[4]);
        acc[5] = fmaf(w1.y, x, acc[5]);
        acc[6] = fmaf(w1.z, x, acc[6]);
        acc[7] = fmaf(w1.w, x, acc[7]);
    }
}

// ---------------- kernels ----------------

// Fused shot weights: fq = qw^T @ shw[0:64], fk = kw^T @ shw[64:128], biases.
__global__ void k_fusew(const float* __restrict__ shw, const float* __restrict__ qw,
                        const float* __restrict__ qb, const float* __restrict__ kw,
                        const float* __restrict__ kb)
{
    int tid = threadIdx.x;
    if (tid < 64) {
        float s = 0.f;
        #pragma unroll 8
        for (int c = 0; c < 64; c++) s = fmaf(shw[c], qw[c*64 + tid], s);
        g_fq[tid] = s;
    } else {
        int t = tid - 64;
        float s = 0.f;
        #pragma unroll 8
        for (int c = 0; c < 64; c++) s = fmaf(shw[64 + c], kw[c*64 + t], s);
        g_fk[t] = s;
    }
    if (tid == 0) {
        float s = 0.f;
        for (int c = 0; c < 64; c++) s = fmaf(shw[c], qb[c], s);
        g_fc[0] = s;
    }
    if (tid == 1) {
        float s = 0.f;
        for (int c = 0; c < 64; c++) s = fmaf(shw[64 + c], kb[c], s);
        g_fc[1] = s;
    }
}

// q,k,v convs (v written transposed) + Sq/Sk rows. Grid 73.
__global__ void k_qkv(const float* __restrict__ d1, const float* __restrict__ d2,
                      const float* __restrict__ qw, const float* __restrict__ qb,
                      const float* __restrict__ kw, const float* __restrict__ kb,
                      const float* __restrict__ vw, const float* __restrict__ vb)
{
    __shared__ float Xs[64*128];
    __shared__ float wT[1024];
    int b = blockIdx.x;
    int tid = threadIdx.x;

    if (b == 72) {  // Sq/Sk: fused-weight rows over desc1/desc2
        if (tid < 64) Xs[tid] = g_fq[tid];
        else if (tid < 128) Xs[tid] = g_fk[tid - 64];
        __syncthreads();
        float aq0 = 0.f, aq1 = 0.f, aq2 = 0.f, ak0 = 0.f, ak1 = 0.f, ak2 = 0.f;
        #pragma unroll 4
        for (int i = 0; i < 64; i++) {
            float fqv = Xs[i], fkv = Xs[64 + i];
            aq0 = fmaf(fqv, d1[i*NN + tid],       aq0);
            aq1 = fmaf(fqv, d1[i*NN + tid + 256], aq1);
            aq2 = fmaf(fqv, d1[i*NN + tid + 512], aq2);
            ak0 = fmaf(fkv, d2[i*NN + tid],       ak0);
            ak1 = fmaf(fkv, d2[i*NN + tid + 256], ak1);
            ak2 = fmaf(fkv, d2[i*NN + tid + 512], ak2);
        }
        float fqb = g_fc[0], fkb = g_fc[1];
        g_Sq[tid]       = aq0 + fqb;
        g_Sq[tid + 256] = aq1 + fqb;
        g_Sq[tid + 512] = aq2 + fqb;
        g_Sk[tid]       = ak0 + fkb;
        g_Sk[tid + 256] = ak1 + fkb;
        g_Sk[tid + 512] = ak2 + fkb;
        return;
    }

    int grp = b / 24, lb = b % 24;
    int rowblk = lb / 6, colblk = lb % 6;
    int o0 = rowblk * 16, c0 = colblk * 128;
    const float *W, *X, *Bb;
    if (grp == 0)      { W = qw; X = d1; Bb = qb; }
    else if (grp == 1) { W = kw; X = d2; Bb = kb; }
    else               { W = vw; X = d2; Bb = vb; }
    fill_W(wT, W, 64, o0, 0);
    fill_X(Xs, X, c0);
    __syncthreads();
    float acc[8] = {};
    gemm16_acc(Xs, wT, acc);
    int c = tid & 127, rg = tid >> 7;
    int obase = o0 + rg * 8;
    if (grp < 2) {
        float* Y = (grp == 0) ? g_q : g_k;
        #pragma unroll
        for (int r = 0; r < 8; r++)
            Y[(obase + r)*NN + c0 + c] = acc[r] + Bb[obase + r];
    } else {
        int n = c0 + c;
        float4 v0, v1;
        v0.x = acc[0] + Bb[obase + 0]; v0.y = acc[1] + Bb[obase + 1];
        v0.z = acc[2] + Bb[obase + 2]; v0.w = acc[3] + Bb[obase + 3];
        v1.x = acc[4] + Bb[obase + 4]; v1.y = acc[5] + Bb[obase + 5];
        v1.z = acc[6] + Bb[obase + 6]; v1.w = acc[7] + Bb[obase + 7];
        *(float4*)&g_vT[n*64 + obase]     = v0;
        *(float4*)&g_vT[n*64 + obase + 4] = v1;
    }
}

// composite inorm+bnorm scale/bias from q (c<64) / k (c>=64). 128 blocks.
__global__ void k_stats1(const float* __restrict__ bn1g, const float* __restrict__ bn1b)
{
    int c = blockIdx.x;
    const float* src = (c < 64) ? (g_q + c*NN) : (g_k + (c - 64)*NN);
    float s = 0.f, s2 = 0.f;
    #pragma unroll
    for (int j = 0; j < 3; j++) {
        float x = src[threadIdx.x + j*256];
        s += x; s2 += x * x;
    }
    __shared__ float r1[8], r2[8];
    s  = bsum_buf(s,  r1);
    s2 = bsum_buf(s2, r2);
    if (threadIdx.x == 0) {
        float m = s * (1.f/NN);
        float v = s2 * (1.f/NN) - m*m;
        float si = rsqrtf(v + 1e-3f);
        float vb = v * si * si;
        float sb = rsqrtf(vb + 1e-5f);
        float scale = si * sb * bn1g[c];
        g_scl1[c] = scale;
        g_bias1[c] = -m * scale + bn1b[c];
    }
}

// A = w1[:,:64] @ relu(norm(q));  B = w1[:,64:] @ relu(norm(k)) + b1. Grid 96.
__global__ void k_AB(const float* __restrict__ w1, const float* __restrict__ b1)
{
    __shared__ float Xs[64*128];
    __shared__ float wT[1024];
    __shared__ float s1[64], bb1[64];
    int b = blockIdx.x;
    int half = b / 48, lb = b % 48;
    int rowblk = lb / 6, colblk = lb % 6;
    int o0 = rowblk * 16, c0 = colblk * 128;
    const float* X = half ? g_k : g_q;
    int so = half ? 64 : 0;
    if (threadIdx.x < 64) {
        s1[threadIdx.x]  = g_scl1[so + threadIdx.x];
        bb1[threadIdx.x] = g_bias1[so + threadIdx.x];
    }
    fill_W(wT, w1, 128, o0, half ? 64 : 0);
    __syncthreads();
    fill_Xnorm(Xs, X, c0, s1, bb1);
    __syncthreads();
    float acc[8] = {};
    gemm16_acc(Xs, wT, acc);
    int c = threadIdx.x & 127, rg = threadIdx.x >> 7;
    int obase = o0 + rg * 8;
    if (half == 0) {
        #pragma unroll
        for (int r = 0; r < 8; r++)
            g_A[(obase + r)*NN + c0 + c] = acc[r];
    } else {
        #pragma unroll
        for (int r = 0; r < 8; r++)
            g_B[(obase + r)*NN + c0 + c] = acc[r] + b1[obase + r];
    }
}

// Stage-2 composite norm coefficients from separable stats. 128 blocks.
__global__ void k_stats2(const float* __restrict__ bn2g, const float* __restrict__ bn2b)
{
    int o = blockIdx.x;
    int tid = threadIdx.x;
    float sA = 0.f, qA = 0.f, sB = 0.f, qB = 0.f;
    #pragma unroll
    for (int j = 0; j < 3; j++) {
        float a = g_A[o*NN + tid + j*256];
        float b = g_B[o*NN + tid + j*256];
        sA += a; qA += a*a; sB += b; qB += b*b;
    }
    __shared__ float r1[8], r2[8], r3[8], r4[8];
    sA = bsum_buf(sA, r1); qA = bsum_buf(qA, r2);
    sB = bsum_buf(sB, r3); qB = bsum_buf(qB, r4);
    if (tid == 0) {
        float mA = sA * (1.f/NN), mB = sB * (1.f/NN);
        float vA = qA * (1.f/NN) - mA*mA;
        float vB = qB * (1.f/NN) - mB*mB;
        float m2 = mA + mB, v2 = vA + vB;
        float si = rsqrtf(v2 + 1e-3f);
        float vb = v2 * si * si;
        float sb = rsqrtf(vb + 1e-5f);
        float scale = si * sb * bn2g[o];
        g_scl2[o] = scale;
        g_bias2[o] = -m2 * scale + bn2b[o];
    }
}

// score_pre[n,m] = sum_o w2[o]*relu(At[o,n]+Bt[o,m]) + b2 + bs + Sq[n] + Sk[m]
// 64x64 tiles, 4x4 register tiles, o-chunked. Grid (12,12).
__global__ void k_score(const float* __restrict__ w2, const float* __restrict__ b2p,
                        const float* __restrict__ bsp, float* __restrict__ out)
{
    __shared__ float As[64*64], Bs[64*64];
    __shared__ float sc[128], bi[128], w2s[128];
    __shared__ float Sqs[64], Sks[64];
    int tid = threadIdx.x;
    int n0 = blockIdx.y * 64, m0 = blockIdx.x * 64;
    if (tid < 128) { sc[tid] = g_scl2[tid]; bi[tid] = g_bias2[tid]; w2s[tid] = w2[tid]; }
    else {
        int t = tid - 128;
        if (t < 64) Sqs[t] = g_Sq[n0 + t];
        else        Sks[t - 64] = g_Sk[m0 + t - 64];
    }
    __syncthreads();

    float acc[4][4] = {};
    int tx = tid & 15, ty = tid >> 4;
    #pragma unroll
    for (int ch = 0; ch < 2; ch++) {
        #pragma unroll
        for (int v = tid; v < 1024; v += 256) {
            int o = v >> 4, t4 = (v & 15) << 2;
            int og = ch * 64 + o;
            float s = sc[og], bb = bi[og];
            float4 a = *(const float4*)&g_A[og*NN + n0 + t4];
            a.x = fmaf(s, a.x, bb); a.y = fmaf(s, a.y, bb);
            a.z = fmaf(s, a.z, bb); a.w = fmaf(s, a.w, bb);
            *(float4*)&As[o*64 + t4] = a;
            float4 bv = *(const float4*)&g_B[og*NN + m0 + t4];
            bv.x *= s; bv.y *= s; bv.z *= s; bv.w *= s;
            *(float4*)&Bs[o*64 + t4] = bv;
        }
        __syncthreads();
        #pragma unroll 2
        for (int o = 0; o < 64; o++) {
            float4 a = *(const float4*)&As[o*64 + ty*4];
            float4 b = *(const float4*)&Bs[o*64 + tx*4];
            float w = w2s[ch*64 + o];
            acc[0][0] = fmaf(w, fmaxf(a.x + b.x, 0.f), acc[0][0]);
            acc[0][1] = fmaf(w, fmaxf(a.x + b.y, 0.f), acc[0][1]);
            acc[0][2] = fmaf(w, fmaxf(a.x + b.z, 0.f), acc[0][2]);
            acc[0][3] = fmaf(w, fmaxf(a.x + b.w, 0.f), acc[0][3]);
            acc[1][0] = fmaf(w, fmaxf(a.y + b.x, 0.f), acc[1][0]);
            acc[1][1] = fmaf(w, fmaxf(a.y + b.y, 0.f), acc[1][1]);
            acc[1][2] = fmaf(w, fmaxf(a.y + b.z, 0.f), acc[1][2]);
            acc[1][3] = fmaf(w, fmaxf(a.y + b.w, 0.f), acc[1][3]);
            acc[2][0] = fmaf(w, fmaxf(a.z + b.x, 0.f), acc[2][0]);
            acc[2][1] = fmaf(w, fmaxf(a.z + b.y, 0.f), acc[2][1]);
            acc[2][2] = fmaf(w, fmaxf(a.z + b.z, 0.f), acc[2][2]);
            acc[2][3] = fmaf(w, fmaxf(a.z + b.w, 0.f), acc[2][3]);
            acc[3][0] = fmaf(w, fmaxf(a.w + b.x, 0.f), acc[3][0]);
            acc[3][1] = fmaf(w, fmaxf(a.w + b.y, 0.f), acc[3][1]);
            acc[3][2] = fmaf(w, fmaxf(a.w + b.z, 0.f), acc[3][2]);
            acc[3][3] = fmaf(w, fmaxf(a.w + b.w, 0.f), acc[3][3]);
        }
        __syncthreads();
    }
    float cc = __ldg(b2p) + __ldg(bsp);
    #pragma unroll
    for (int rn = 0; rn < 4; rn++) {
        int n = n0 + ty*4 + rn;
        float sq = Sqs[ty*4 + rn] + cc;
        float4 o4;
        o4.x = acc[rn][0] + sq + Sks[tx*4 + 0];
        o4.y = acc[rn][1] + sq + Sks[tx*4 + 1];
        o4.z = acc[rn][2] + sq + Sks[tx*4 + 2];
        o4.w = acc[rn][3] + sq + Sks[tx*4 + 3];
        *(float4*)&out[n*NN + m0 + tx*4] = o4;
    }
}

// warp-per-row softmax, in place. 96 blocks x 256.
__global__ void k_softmax(float* __restrict__ score)
{
    int row = blockIdx.x * 8 + (threadIdx.x >> 5);
    int lane = threadIdx.x & 31;
    float* p = score + row * NN;
    float v[24];
    float mx = -1e30f;
    #pragma unroll
    for (int i = 0; i < 24; i++) { v[i] = p[lane + i*32]; mx = fmaxf(mx, v[i]); }
    #pragma unroll
    for (int o = 16; o; o >>= 1) mx = fmaxf(mx, __shfl_xor_sync(0xffffffffu, mx, o));
    float s = 0.f;
    #pragma unroll
    for (int i = 0; i < 24; i++) { v[i] = __expf(v[i] - mx); s += v[i]; }
    #pragma unroll
    for (int o = 16; o; o >>= 1) s += __shfl_xor_sync(0xffffffffu, s, o);
    float inv = 1.f / s;
    #pragma unroll
    for (int i = 0; i < 24; i++) p[lane + i*32] = v[i] * inv;
}

// av partials: 48 n-tiles x 4 k-splits.
__global__ void k_av(const float* __restrict__ score)
{
    int bx = blockIdx.x;
    int nt = bx % 48, ks = bx / 48;
    int n0 = nt * 16;
    int tid = threadIdx.x;
    __shared__ float Vs[64][64];
    __shared__ float Ps[16][64];
    int d0  = (tid & 31) * 2;
    int nl0 = (tid >> 5) * 2;
    float a00 = 0.f, a01 = 0.f, a10 = 0.f, a11 = 0.f;
    for (int c = 0; c < 3; c++) {
        int mb = ks * 192 + c * 64;
        for (int idx = tid; idx < 64*64; idx += 256)
            Vs[idx >> 6][idx & 63] = g_vT[(mb + (idx >> 6))*64 + (idx & 63)];
        for (int idx = tid; idx < 16*64; idx += 256)
            Ps[idx >> 6][idx & 63] = score[(n0 + (idx >> 6))*NN + mb + (idx & 63)];
        __syncthreads();
        #pragma unroll 4
        for (int m = 0; m < 64; m++) {
            float2 vv = *(const float2*)&Vs[m][d0];
            float p0 = Ps[nl0][m], p1 = Ps[nl0 + 1][m];
            a00 = fmaf(p0, vv.x, a00); a01 = fmaf(p0, vv.y, a01);
            a10 = fmaf(p1, vv.x, a10); a11 = fmaf(p1, vv.y, a11);
        }
        __syncthreads();
    }
    float* dst = g_avp + ks * (64*NN);
    dst[d0*NN + n0 + nl0]           = a00;
    dst[(d0 + 1)*NN + n0 + nl0]     = a01;
    dst[d0*NN + n0 + nl0 + 1]       = a10;
    dst[(d0 + 1)*NN + n0 + nl0 + 1] = a11;
}

__global__ void k_avred()
{
    int i = blockIdx.x * 256 + threadIdx.x;
    g_av[i] = g_avp[i] + g_avp[64*NN + i] + g_avp[2*64*NN + i] + g_avp[3*64*NN + i];
}

// mh conv. Grid 24.
__global__ void k_mh(const float* __restrict__ mhw, const float* __restrict__ mhb)
{
    __shared__ float Xs[64*128];
    __shared__ float wT[1024];
    int lb = blockIdx.x;
    int rowblk = lb / 6, colblk = lb % 6;
    int o0 = rowblk * 16, c0 = colblk * 128;
    fill_W(wT, mhw, 64, o0, 0);
    fill_X(Xs, g_av, c0);
    __syncthreads();
    float acc[8] = {};
    gemm16_acc(Xs, wT, acc);
    int c = threadIdx.x & 127, rg = threadIdx.x >> 7;
    int obase = o0 + rg * 8;
    #pragma unroll
    for (int r = 0; r < 8; r++)
        g_av2[(obase + r)*NN + c0 + c] = acc[r] + mhb[obase + r];
}

// g1 = cat_w1 @ [desc1; av2] + cat_b1. Grid 48, K=128 in two chunks.
__global__ void k_cat1(const float* __restrict__ w1, const float* __restrict__ desc1,
                       const float* __restrict__ b1)
{
    __shared__ float Xs[64*128];
    __shared__ float wT[1024];
    int lb = blockIdx.x;
    int rowblk = lb / 6, colblk = lb % 6;
    int o0 = rowblk * 16, c0 = colblk * 128;
    float acc[8] = {};
    fill_W(wT, w1, 128, o0, 0);
    fill_X(Xs, desc1, c0);
    __syncthreads();
    gemm16_acc(Xs, wT, acc);
    __syncthreads();
    fill_W(wT, w1, 128, o0, 64);
    fill_X(Xs, g_av2, c0);
    __syncthreads();
    gemm16_acc(Xs, wT, acc);
    int c = threadIdx.x & 127, rg = threadIdx.x >> 7;
    int obase = o0 + rg * 8;
    #pragma unroll
    for (int r = 0; r < 8; r++)
        g_g1[(obase + r)*NN + c0 + c] = acc[r] + b1[obase + r];
}

// bnorm1d + relu in place on g1. 128 blocks.
__global__ void k_bn1d(const float* __restrict__ cbg, const float* __restrict__ cbb)
{
    int o = blockIdx.x;
    int tid = threadIdx.x;
    float s = 0.f, s2 = 0.f;
    #pragma unroll
    for (int j = 0; j < 3; j++) {
        float x = g_g1[o*NN + tid + j*256];
        s += x; s2 += x*x;
    }
    __shared__ float r1[8], r2[8];
    s = bsum_buf(s, r1); s2 = bsum_buf(s2, r2);
    __shared__ float sc_b[2];
    if (tid == 0) {
        float m = s * (1.f/NN);
        float v = s2 * (1.f/NN) - m*m;
        float scale = rsqrtf(v + 1e-5f) * cbg[o];
        sc_b[0] = scale;
        sc_b[1] = -m * scale + cbb[o];
    }
    __syncthreads();
    float scale = sc_b[0], bias = sc_b[1];
    #pragma unroll
    for (int j = 0; j < 3; j++) {
        int idx = o*NN + tid + j*256;
        g_g1[idx] = fmaxf(fmaf(scale, g_g1[idx], bias), 0.f);
    }
}

// out_desc = desc1 + cat_w2 @ g1 + cat_b2. Grid 24, K=128 two chunks.
__global__ void k_final(const float* __restrict__ cw2, const float* __restrict__ cb2,
                        const float* __restrict__ desc1, float* __restrict__ out)
{
    __shared__ float Xs[64*128];
    __shared__ float wT[1024];
    int lb = blockIdx.x;
    int rowblk = lb / 6, colblk = lb % 6;
    int o0 = rowblk * 16, c0 = colblk * 128;
    float acc[8] = {};
    fill_W(wT, cw2, 128, o0, 0);
    fill_X(Xs, g_g1, c0);
    __syncthreads();
    gemm16_acc(Xs, wT, acc);
    __syncthreads();
    fill_W(wT, cw2, 128, o0, 64);
    fill_X(Xs, g_g1 + 64*NN, c0);
    __syncthreads();
    gemm16_acc(Xs, wT, acc);
    int c = threadIdx.x & 127, rg = threadIdx.x >> 7;
    int obase = o0 + rg * 8;
    #pragma unroll
    for (int r = 0; r < 8; r++)
        out[(obase + r)*NN + c0 + c] =
            acc[r] + cb2[obase + r] + desc1[(obase + r)*NN + c0 + c];
}

// ---------------- launch ----------------
extern "C" void kernel_launch(void* const* d_in, const int* in_sizes, int n_in,
                              void* d_out, int out_size)
{
    const float* desc1 = (const float*)d_in[0];
    const float* desc2 = (const float*)d_in[1];
    const float* qw  = (const float*)d_in[2];  const float* qb  = (const float*)d_in[3];
    const float* kw  = (const float*)d_in[4];  const float* kb  = (const float*)d_in[5];
    const float* vw  = (const float*)d_in[6];  const float* vb  = (const float*)d_in[7];
    const float* mhw = (const float*)d_in[8];  const float* mhb = (const float*)d_in[9];
    const float* cw1 = (const float*)d_in[10]; const float* cb1 = (const float*)d_in[11];
    const float* cbg = (const float*)d_in[12]; const float* cbb = (const float*)d_in[13];
    const float* cw2 = (const float*)d_in[14]; const float* cb2 = (const float*)d_in[15];
    const float* shw = (const float*)d_in[16]; const float* shb = (const float*)d_in[17];
    const float* bn1g = (const float*)d_in[18]; const float* bn1b = (const float*)d_in[19];
    const float* sw1 = (const float*)d_in[20]; const float* sb1 = (const float*)d_in[21];
    const float* bn2g = (const float*)d_in[22]; const float* bn2b = (const float*)d_in[23];
    const float* sw2 = (const float*)d_in[24]; const float* sb2 = (const float*)d_in[25];

    float* out = (float*)d_out;
    float* out_desc  = out;
    float* out_score = out + 64 * NN;

    k_fusew<<<1, 128>>>(shw, qw, qb, kw, kb);
    k_qkv<<<73, 256>>>(desc1, desc2, qw, qb, kw, kb, vw, vb);
    k_stats1<<<128, 256>>>(bn1g, bn1b);
    k_AB<<<96, 256>>>(sw1, sb1);
    k_stats2<<<128, 256>>>(bn2g, bn2b);
    k_score<<<dim3(12, 12), 256>>>(sw2, sb2, shb, out_score);
    k_softmax<<<96, 256>>>(out_score);
    k_av<<<192, 256>>>(out_score);
    k_avred<<<192, 256>>>();
    k_mh<<<24, 256>>>(mhw, mhb);
    k_cat1<<<48, 256>>>(cw1, desc1, cb1);
    k_bn1d<<<128, 256>>>(cbg, cbb);
    k_final<<<24, 256>>>(cw2, cb2, desc1, out_desc);
}